// round 4
// baseline (speedup 1.0000x reference)
#include <cuda_runtime.h>
#include <cuda_bf16.h>
#include <cstdint>

// ============================================================================
// Problem constants
// ============================================================================
#define PADV (-10000.0f)
static constexpr int BB = 512;
static constexpr int NN = 2048;
static constexpr int FF = 16;
static constexpr int HH = 128;
static constexpr int TILES_PER_B = NN / 128;         // 16
static constexpr int NSLOTS = BB * TILES_PER_B;      // 8192
static constexpr int PHI_GRID = 148;
static constexpr int PHI_THREADS = 512;              // 16 warps

// ============================================================================
// Device globals (scratch; allocation-free rule)
// ============================================================================
__device__ int   g_len[BB];
__device__ int   g_ticket;
__device__ float g_partial[(size_t)NSLOTS * HH];     // 4 MB partial pooled sums

// ============================================================================
// SMEM layout (dynamic, phi kernel)  — 1 CTA/SM, ~226.5 KB
// Weight matrices stored as W[n][k] bf16, row stride 256B, 16B-chunk XOR swizzle
// ============================================================================
static constexpr int W1H_OFF  = 0;
static constexpr int W1L_OFF  = 32768;
static constexpr int W2H_OFF  = 65536;
static constexpr int W2L_OFF  = 98304;
static constexpr int W3H_OFF  = 131072;
static constexpr int W3L_OFF  = 163840;
static constexpr int A_OFF    = 196608;   // 128 rows x 256B activation buffer (bf16)
static constexpr int BIAS_OFF = 229376;   // 4 x 128 fp32
static constexpr int SLOT_OFF = 231424;   // int
static constexpr int SMEM_TOTAL = 231936;

// ============================================================================
// PTX helpers: ldmatrix + mma.sync (arch-generic, works on plain sm_103)
// ============================================================================
__device__ __forceinline__ uint32_t smem_to_u32(const void* smem_ptr) {
    uint32_t addr;
    asm("{ .reg .u64 tmp; cvta.to.shared.u64 tmp, %1; cvt.u32.u64 %0, tmp; }"
        : "=r"(addr) : "l"(smem_ptr));
    return addr;
}

__device__ __forceinline__ void ldsm4(uint32_t (&r)[4], uint32_t addr) {
    asm volatile("ldmatrix.sync.aligned.m8n8.x4.shared.b16 {%0,%1,%2,%3}, [%4];"
        : "=r"(r[0]), "=r"(r[1]), "=r"(r[2]), "=r"(r[3]) : "r"(addr));
}

__device__ __forceinline__ void mma16816(float (&c)[4], const uint32_t (&a)[4],
                                         uint32_t b0, uint32_t b1) {
    asm volatile(
        "mma.sync.aligned.m16n8k16.row.col.f32.bf16.bf16.f32 "
        "{%0,%1,%2,%3}, {%4,%5,%6,%7}, {%8,%9}, {%0,%1,%2,%3};"
        : "+f"(c[0]), "+f"(c[1]), "+f"(c[2]), "+f"(c[3])
        : "r"(a[0]), "r"(a[1]), "r"(a[2]), "r"(a[3]), "r"(b0), "r"(b1));
}

// pack (even, odd) floats -> bf16x2 (lo = even, hi = odd)
__device__ __forceinline__ uint32_t pack_bf16x2(float e, float o) {
    uint32_t r;
    asm("cvt.rn.satfinite.bf16x2.f32 %0, %1, %2;" : "=r"(r) : "f"(o), "f"(e));
    return r;
}

// swizzled byte offset inside a [128 rows x 256B] matrix: (row, 2-byte col k)
__device__ __forceinline__ uint32_t mswz(int row, int k) {
    return (uint32_t)row * 256u + (((uint32_t)k * 2u) ^ (((uint32_t)row & 7u) << 4));
}

// ============================================================================
// Kernel 1: lengths (binary search — pad is a suffix) + ticket reset
// ============================================================================
__global__ void len_kernel(const float* __restrict__ x) {
    int b = threadIdx.x;
    if (b == 0) g_ticket = 0;
    if (b < BB) {
        int lo = 0, hi = NN;
        while (lo < hi) {
            int mid = (lo + hi) >> 1;
            const float* r = x + ((size_t)b * NN + mid) * FF;
            bool pad = true;
            #pragma unroll
            for (int f = 0; f < FF; f++) pad = pad && (r[f] == PADV);
            if (pad) hi = mid; else lo = mid + 1;
        }
        g_len[b] = lo;
    }
}

// ============================================================================
// Kernel 2: persistent phi — HMMA (mma.sync bf16, hi/lo split), weights in SMEM
// ============================================================================
__global__ void __launch_bounds__(PHI_THREADS, 1)
phi_kernel(const float* __restrict__ x,
           const float* __restrict__ w0, const float* __restrict__ b0,
           const float* __restrict__ w1, const float* __restrict__ b1,
           const float* __restrict__ w2, const float* __restrict__ b2,
           const float* __restrict__ w3, const float* __restrict__ b3) {
    extern __shared__ __align__(1024) char smem[];
    const int tid  = threadIdx.x;
    const int wid  = tid >> 5;
    const int lane = tid & 31;
    const int rg   = wid >> 1;      // row-group 0..7 (16 rows each)
    const int ch   = wid & 1;       // col-half 0..1 (64 cols each)
    const uint32_t smem_base = smem_to_u32(smem);
    const uint32_t Ab = smem_base + A_OFF;

    // ---- biases to SMEM ----
    {
        float* bs = (float*)(smem + BIAS_OFF);
        if (tid < HH) {
            bs[tid]          = b0[tid];
            bs[HH + tid]     = b1[tid];
            bs[2 * HH + tid] = b2[tid];
            bs[3 * HH + tid] = b3[tid];
        }
    }
    // ---- W1..W3 -> bf16 hi/lo split, W[n][k] layout, swizzled ----
    {
        const float* Wg[3] = { w1, w2, w3 };
        const int   Hh[3] = { W1H_OFF, W2H_OFF, W3H_OFF };
        const int   Ll[3] = { W1L_OFF, W2L_OFF, W3L_OFF };
        for (int L = 0; L < 3; L++) {
            const float* W = Wg[L];
            for (int i = tid; i < HH * HH; i += PHI_THREADS) {
                int k = i >> 7, n = i & 127;        // gmem: W[k][n]
                float v = W[i];
                __nv_bfloat16 h = __float2bfloat16(v);
                float lo = v - __bfloat162float(h);
                __nv_bfloat16 l = __float2bfloat16(lo);
                uint32_t off = mswz(n, k);
                *reinterpret_cast<__nv_bfloat16*>(smem + Hh[L] + off) = h;
                *reinterpret_cast<__nv_bfloat16*>(smem + Ll[L] + off) = l;
            }
        }
    }
    __syncthreads();

    const float* bias = (const float*)(smem + BIAS_OFF);
    int* s_slot = (int*)(smem + SLOT_OFF);
    float* red  = (float*)(smem + A_OFF);   // reused after layer-3 mma
    const uint32_t WH[3] = { smem_base + W1H_OFF, smem_base + W2H_OFF, smem_base + W3H_OFF };
    const uint32_t WL[3] = { smem_base + W1L_OFF, smem_base + W2L_OFF, smem_base + W3L_OFF };

    while (true) {
        __syncthreads();                    // protects s_slot + red/A reuse
        if (tid == 0) *s_slot = atomicAdd(&g_ticket, 1);
        __syncthreads();
        const int slot = *s_slot;
        if (slot >= NSLOTS) break;
        const int b = slot >> 4, t = slot & 15;
        const int len = g_len[b];
        const int start = t * 128;
        if (start >= len) continue;
        const int valid = min(128, len - start);

        // ================= layer 0 (K=16) in SIMT fp32, straight from gmem ====
        {
            const int c0 = lane * 4;
            float4 bw = *(const float4*)(bias + c0);
            float acc[8][4];
            #pragma unroll
            for (int r = 0; r < 8; r++) {
                acc[r][0] = bw.x; acc[r][1] = bw.y; acc[r][2] = bw.z; acc[r][3] = bw.w;
            }
            const float* xp = x + ((size_t)b * NN + start + wid * 8) * FF;
            #pragma unroll
            for (int k = 0; k < FF; k++) {
                float4 wv = *(const float4*)(w0 + k * HH + c0);
                #pragma unroll
                for (int r = 0; r < 8; r++) {
                    float xv = __ldg(xp + r * FF + k);   // warp-uniform, L1 broadcast
                    acc[r][0] = fmaf(xv, wv.x, acc[r][0]);
                    acc[r][1] = fmaf(xv, wv.y, acc[r][1]);
                    acc[r][2] = fmaf(xv, wv.z, acc[r][2]);
                    acc[r][3] = fmaf(xv, wv.w, acc[r][3]);
                }
            }
            #pragma unroll
            for (int r = 0; r < 8; r++) {
                int row = wid * 8 + r;
                uint32_t rb = Ab + (uint32_t)row * 256u;
                uint32_t sw = ((uint32_t)row & 7u) << 4;
                uint32_t p0 = pack_bf16x2(fmaxf(acc[r][0], 0.f), fmaxf(acc[r][1], 0.f));
                uint32_t p1 = pack_bf16x2(fmaxf(acc[r][2], 0.f), fmaxf(acc[r][3], 0.f));
                *(uint32_t*)(smem + (rb - smem_base) + (((uint32_t)(lane * 8)) ^ sw))     = p0;
                *(uint32_t*)(smem + (rb - smem_base) + (((uint32_t)(lane * 8 + 4)) ^ sw)) = p1;
            }
        }
        __syncthreads();

        // ================= layers 1..3 via mma.sync (hi + lo over same A) =====
        for (int L = 0; L < 3; L++) {
            float c[8][4];
            #pragma unroll
            for (int nb = 0; nb < 8; nb++)
                #pragma unroll
                for (int j = 0; j < 4; j++) c[nb][j] = 0.f;

            const uint32_t Whi = WH[L], Wlo = WL[L];
            #pragma unroll
            for (int kb = 0; kb < 8; kb++) {
                // A fragment: rows rg*16..+15, k = kb*16..+15
                uint32_t a[4];
                {
                    int ar = rg * 16 + (lane & 15);
                    int ak = kb * 16 + ((lane >> 4) << 3);
                    ldsm4(a, Ab + mswz(ar, ak));
                }
                #pragma unroll
                for (int p = 0; p < 4; p++) {
                    int n = ch * 64 + p * 16 + (lane & 7) + ((lane >> 4) << 3);
                    int k = kb * 16 + (((lane >> 3) & 1) << 3);
                    uint32_t boff = mswz(n, k);
                    uint32_t bh[4], bl[4];
                    ldsm4(bh, Whi + boff);
                    ldsm4(bl, Wlo + boff);
                    mma16816(c[2 * p],     a, bh[0], bh[1]);
                    mma16816(c[2 * p + 1], a, bh[2], bh[3]);
                    mma16816(c[2 * p],     a, bl[0], bl[1]);
                    mma16816(c[2 * p + 1], a, bl[2], bl[3]);
                }
            }
            __syncthreads();   // all warps done READING A (and, for L=2, before red reuse)

            if (L < 2) {
                // bias + ReLU -> bf16 -> A (next layer's operand)
                const float* bl_ = bias + (L + 1) * HH;
                const int r0 = rg * 16 + (lane >> 2);
                const int r1 = r0 + 8;
                #pragma unroll
                for (int nb = 0; nb < 8; nb++) {
                    int col = ch * 64 + nb * 8 + (lane & 3) * 2;
                    float be = bl_[col], bo = bl_[col + 1];
                    uint32_t p0 = pack_bf16x2(fmaxf(c[nb][0] + be, 0.f),
                                              fmaxf(c[nb][1] + bo, 0.f));
                    uint32_t p1 = pack_bf16x2(fmaxf(c[nb][2] + be, 0.f),
                                              fmaxf(c[nb][3] + bo, 0.f));
                    *(uint32_t*)(smem + A_OFF + mswz(r0, col)) = p0;
                    *(uint32_t*)(smem + A_OFF + mswz(r1, col)) = p1;
                }
                __syncthreads();
            } else if (L == 1) {
                // unreachable; kept for symmetry
            }

            if (L == 2) {
                // wait: L==2 is the LAST mma layer here? No — layers 1..3 are L=0,1,2
                // epilogue for final layer (phi layer 3): bias + ReLU + masked col-sum
                const float* b3s = bias + 3 * HH;
                const int r0 = rg * 16 + (lane >> 2);
                const int r1 = r0 + 8;
                const float m0 = (r0 < valid) ? 1.f : 0.f;
                const float m1 = (r1 < valid) ? 1.f : 0.f;
                #pragma unroll
                for (int nb = 0; nb < 8; nb++) {
                    int col = ch * 64 + nb * 8 + (lane & 3) * 2;
                    float be = b3s[col], bo = b3s[col + 1];
                    float s0 = m0 * fmaxf(c[nb][0] + be, 0.f) + m1 * fmaxf(c[nb][2] + be, 0.f);
                    float s1 = m0 * fmaxf(c[nb][1] + bo, 0.f) + m1 * fmaxf(c[nb][3] + bo, 0.f);
                    #pragma unroll
                    for (int off = 4; off < 32; off <<= 1) {
                        s0 += __shfl_xor_sync(0xFFFFFFFFu, s0, off);
                        s1 += __shfl_xor_sync(0xFFFFFFFFu, s1, off);
                    }
                    if (lane < 4) {
                        int cc = ch * 64 + nb * 8 + lane * 2;
                        red[rg * HH + cc]     = s0;
                        red[rg * HH + cc + 1] = s1;
                    }
                }
                __syncthreads();
                if (tid < HH) {
                    float s = 0.f;
                    #pragma unroll
                    for (int g = 0; g < 8; g++) s += red[g * HH + tid];
                    g_partial[(size_t)slot * HH + tid] = s;
                }
            }
        }
    }
}

// ============================================================================
// Kernel 3: rho (fp32 SIMT), deterministic fixed-order partial reduction
// ============================================================================
__global__ void __launch_bounds__(128)
rho_kernel(const float* __restrict__ w0, const float* __restrict__ b0,
           const float* __restrict__ w1, const float* __restrict__ b1,
           const float* __restrict__ w2, const float* __restrict__ b2,
           const float* __restrict__ w3, const float* __restrict__ b3,
           float* __restrict__ out) {
    __shared__ float s_in[HH];
    __shared__ float s_red[HH];
    const int b = blockIdx.x, j = threadIdx.x;
    const int len = g_len[b];
    const int nt = (len + 127) >> 7;

    float acc = 0.f;
    for (int t = 0; t < nt; t++)
        acc += g_partial[((size_t)b * TILES_PER_B + t) * HH + j];
    s_in[j] = acc;
    __syncthreads();

    const float* Ws[3] = { w0, w1, w2 };
    const float* Bs[3] = { b0, b1, b2 };
    for (int L = 0; L < 3; L++) {
        float v = Bs[L][j];
        const float* W = Ws[L];
        #pragma unroll 8
        for (int k = 0; k < HH; k++) v += s_in[k] * W[k * HH + j];
        v = fmaxf(v, 0.f);
        __syncthreads();
        s_in[j] = v;
        __syncthreads();
    }
    s_red[j] = s_in[j] * w3[j];
    __syncthreads();
    if (j == 0) {
        float s = b3[0];
        #pragma unroll 8
        for (int k = 0; k < HH; k++) s += s_red[k];
        out[b] = s;
    }
}

// ============================================================================
// kernel_launch
// ============================================================================
extern "C" void kernel_launch(void* const* d_in, const int* in_sizes, int n_in,
                              void* d_out, int out_size) {
    const float* x   = (const float*)d_in[0];
    const float* pw0 = (const float*)d_in[1];
    const float* pb0 = (const float*)d_in[2];
    const float* pw1 = (const float*)d_in[3];
    const float* pb1 = (const float*)d_in[4];
    const float* pw2 = (const float*)d_in[5];
    const float* pb2 = (const float*)d_in[6];
    const float* pw3 = (const float*)d_in[7];
    const float* pb3 = (const float*)d_in[8];
    const float* rw0 = (const float*)d_in[9];
    const float* rb0 = (const float*)d_in[10];
    const float* rw1 = (const float*)d_in[11];
    const float* rb1 = (const float*)d_in[12];
    const float* rw2 = (const float*)d_in[13];
    const float* rb2 = (const float*)d_in[14];
    const float* rw3 = (const float*)d_in[15];
    const float* rb3 = (const float*)d_in[16];

    static bool attr_set = false;
    if (!attr_set) {
        cudaFuncSetAttribute(phi_kernel, cudaFuncAttributeMaxDynamicSharedMemorySize, SMEM_TOTAL);
        attr_set = true;
    }

    len_kernel<<<1, 512>>>(x);
    phi_kernel<<<PHI_GRID, PHI_THREADS, SMEM_TOTAL>>>(x, pw0, pb0, pw1, pb1, pw2, pb2, pw3, pb3);
    rho_kernel<<<BB, 128>>>(rw0, rb0, rw1, rb1, rw2, rb2, rw3, rb3, (float*)d_out);
}

// round 7
// speedup vs baseline: 1.8007x; 1.8007x over previous
#include <cuda_runtime.h>
#include <cuda_fp16.h>
#include <cstdint>

// ============================================================================
// Problem constants
// ============================================================================
#define PADV (-10000.0f)
static constexpr int BB = 512;
static constexpr int NN = 2048;
static constexpr int FF = 16;
static constexpr int HH = 128;
static constexpr int TILES_PER_B = NN / 128;         // 16
static constexpr int NSLOTS = BB * TILES_PER_B;      // 8192
static constexpr int PHI_GRID = 148;
static constexpr int PHI_THREADS = 512;              // 16 warps

// ============================================================================
// Device globals (scratch; allocation-free rule)
// ============================================================================
__device__ int   g_len[BB];
__device__ int   g_ticket;
__device__ int   g_nwork;
__device__ int   g_work[NSLOTS];
__device__ float g_partial[(size_t)NSLOTS * HH];     // partial pooled sums

// ============================================================================
// SMEM layout (dynamic, phi kernel) — 1 CTA/SM, ~183 KB
// W1..W3: fp16 W[n][k], row stride 256B, 16B-chunk XOR swizzle
// W0/A2 : fp16, row stride 48B (conflict-free for ldmatrix, no swizzle)
// ============================================================================
static constexpr int W1_OFF   = 0;
static constexpr int W2_OFF   = 32768;
static constexpr int W3_OFF   = 65536;
static constexpr int W0_OFF   = 98304;    // 128 n-rows x 48B = 6144
static constexpr int A2_OFF   = 104448;   // 128 rows x 48B   = 6144 (x tile fp16)
static constexpr int AP0_OFF  = 110592;   // ping activation, 32 KB
static constexpr int AP1_OFF  = 143360;   // pong activation, 32 KB
static constexpr int BIAS_OFF = 176128;   // 4 x 128 fp32
static constexpr int RED_OFF  = 178176;   // 8 x 128 fp32
static constexpr int SLOT_OFF = 182272;
static constexpr int SMEM_TOTAL = 182784;

// ============================================================================
// PTX helpers (arch-generic: ldmatrix + mma.sync fp16)
// ============================================================================
__device__ __forceinline__ uint32_t smem_to_u32(const void* smem_ptr) {
    uint32_t addr;
    asm("{ .reg .u64 tmp; cvta.to.shared.u64 tmp, %1; cvt.u32.u64 %0, tmp; }"
        : "=r"(addr) : "l"(smem_ptr));
    return addr;
}

__device__ __forceinline__ void ldsm4(uint32_t (&r)[4], uint32_t addr) {
    asm volatile("ldmatrix.sync.aligned.m8n8.x4.shared.b16 {%0,%1,%2,%3}, [%4];"
        : "=r"(r[0]), "=r"(r[1]), "=r"(r[2]), "=r"(r[3]) : "r"(addr));
}

__device__ __forceinline__ void mma16816(float (&c)[4], const uint32_t (&a)[4],
                                         uint32_t b0, uint32_t b1) {
    asm volatile(
        "mma.sync.aligned.m16n8k16.row.col.f32.f16.f16.f32 "
        "{%0,%1,%2,%3}, {%4,%5,%6,%7}, {%8,%9}, {%0,%1,%2,%3};"
        : "+f"(c[0]), "+f"(c[1]), "+f"(c[2]), "+f"(c[3])
        : "r"(a[0]), "r"(a[1]), "r"(a[2]), "r"(a[3]), "r"(b0), "r"(b1));
}

// pack (even, odd) floats -> f16x2 (lo = even, hi = odd), saturate-to-finite
__device__ __forceinline__ uint32_t pack_f16x2(float e, float o) {
    uint32_t r;
    asm("cvt.rn.satfinite.f16x2.f32 %0, %1, %2;" : "=r"(r) : "f"(o), "f"(e));
    return r;
}

// swizzled byte offset inside a [128 rows x 256B] matrix: (row, 2-byte col k)
__device__ __forceinline__ uint32_t mswz(int row, int k) {
    return (uint32_t)row * 256u + (((uint32_t)k * 2u) ^ (((uint32_t)row & 7u) << 4));
}

// ============================================================================
// Kernel 0: reset counters (must precede len_kernel's atomics)
// ============================================================================
__global__ void reset_kernel() { g_ticket = 0; g_nwork = 0; }

// ============================================================================
// Kernel 1: lengths — warp-parallel 3-probe search + compact work queue
// ============================================================================
__device__ __forceinline__ bool row_is_pad(const float* xb, int row) {
    float4 v = __ldg((const float4*)(xb + (size_t)row * FF));
    return (v.x == PADV) & (v.y == PADV) & (v.z == PADV) & (v.w == PADV);
}

__global__ void __launch_bounds__(256)
len_kernel(const float* __restrict__ x) {
    const int wid  = threadIdx.x >> 5;
    const int lane = threadIdx.x & 31;
    const int b = blockIdx.x * 8 + wid;
    if (b >= BB) return;
    const float* xb = x + (size_t)b * NN * FF;

    // level 1: granularity 64
    bool p1 = row_is_pad(xb, lane * 64);
    unsigned m1 = __ballot_sync(0xFFFFFFFFu, p1);
    int L;                          // first_pad in (L, L+64]
    if (m1 == 0) L = 2048 - 64;
    else         L = (__ffs(m1) - 1 - 1) * 64;   // bit0 never set (len >= 1)

    // level 2: granularity 2 — probe L+1+2*lane
    bool p2 = row_is_pad(xb, L + 1 + 2 * lane);
    unsigned m2 = __ballot_sync(0xFFFFFFFFu, p2);
    int len;
    if (m2 == 0) {
        len = L + 64;
    } else {
        int t0 = __ffs(m2) - 1;
        // first_pad in {L+2*t0, L+2*t0+1}; resolve with one probe (lane 0 result broadcast)
        bool pm = row_is_pad(xb, L + 2 * t0);
        unsigned mm = __ballot_sync(0xFFFFFFFFu, pm);
        len = (mm & 1u) ? (L + 2 * t0) : (L + 2 * t0 + 1);
    }
    if (lane == 0) {
        g_len[b] = len;
        int nt = (len + 127) >> 7;
        int base = atomicAdd(&g_nwork, nt);
        for (int t = 0; t < nt; t++) g_work[base + t] = (b << 4) | t;
    }
}

// ============================================================================
// Kernel 2: persistent phi — fp16 single-pass mma.sync, weights in SMEM
// ============================================================================
__global__ void __launch_bounds__(PHI_THREADS, 1)
phi_kernel(const float* __restrict__ x,
           const float* __restrict__ w0, const float* __restrict__ b0,
           const float* __restrict__ w1, const float* __restrict__ b1,
           const float* __restrict__ w2, const float* __restrict__ b2,
           const float* __restrict__ w3, const float* __restrict__ b3) {
    extern __shared__ __align__(1024) char smem[];
    const int tid  = threadIdx.x;
    const int wid  = tid >> 5;
    const int lane = tid & 31;
    const int rg   = wid >> 1;      // row-group 0..7 (16 rows each)
    const int ch   = wid & 1;       // col-half 0..1 (64 cols each)
    const uint32_t smem_base = smem_to_u32(smem);

    // ---- biases to SMEM ----
    {
        float* bs = (float*)(smem + BIAS_OFF);
        if (tid < HH) {
            bs[tid]          = b0[tid];
            bs[HH + tid]     = b1[tid];
            bs[2 * HH + tid] = b2[tid];
            bs[3 * HH + tid] = b3[tid];
        }
    }
    // ---- W1..W3 -> fp16, W[n][k] swizzled layout ----
    {
        const float* Wg[3] = { w1, w2, w3 };
        const int    Wo[3] = { W1_OFF, W2_OFF, W3_OFF };
        for (int Li = 0; Li < 3; Li++) {
            const float* W = Wg[Li];
            for (int i = tid; i < HH * HH; i += PHI_THREADS) {
                int k = i >> 7, n = i & 127;        // gmem: W[k][n]
                *reinterpret_cast<__half*>(smem + Wo[Li] + mswz(n, k)) = __float2half(W[i]);
            }
        }
    }
    // ---- W0 [16][128] -> fp16 W0[n][k], 48B row stride ----
    for (int i = tid; i < FF * HH; i += PHI_THREADS) {
        int k = i >> 7, n = i & 127;
        *reinterpret_cast<__half*>(smem + W0_OFF + n * 48 + k * 2) = __float2half(w0[i]);
    }
    __syncthreads();

    const float* bias = (const float*)(smem + BIAS_OFF);
    int* s_slot = (int*)(smem + SLOT_OFF);
    float* red  = (float*)(smem + RED_OFF);
    const uint32_t WB[3] = { smem_base + W1_OFF, smem_base + W2_OFF, smem_base + W3_OFF };
    const uint32_t W0b = smem_base + W0_OFF;
    const uint32_t A2b = smem_base + A2_OFF;
    const uint32_t AB[2] = { smem_base + AP0_OFF, smem_base + AP1_OFF };

    // per-thread fragment coordinates
    const int ar = rg * 16 + (lane & 15);             // ldsm A row
    const int akh = (lane >> 4) << 3;                 // ldsm A k-offset (0/8)
    const int bn = ch * 64 + (lane & 7) + ((lane >> 4) << 3);  // ldsm B n base (+p*16)
    const int bk = ((lane >> 3) & 1) << 3;            // ldsm B k-offset (0/8)
    const int r0 = rg * 16 + (lane >> 2);             // C row (frag rows r0, r0+8)
    const int cc0 = ch * 64 + (lane & 3) * 2;         // C col base (+nb*8)

    while (true) {
        __syncthreads();                    // protects s_slot + buffer reuse
        if (tid == 0) *s_slot = atomicAdd(&g_ticket, 1);
        __syncthreads();
        const int idx = *s_slot;
        if (idx >= g_nwork) break;
        const int slot = g_work[idx];
        const int b = slot >> 4, t = slot & 15;
        const int valid = min(128, g_len[b] - t * 128);

        // ---- stage x tile -> A2 as fp16 (48B stride), zero invalid rows ----
        {
            int row = tid >> 2, seg = tid & 3;
            float4 v = __ldg((const float4*)(x + ((size_t)b * NN + t * 128 + row) * FF + seg * 4));
            uint32_t p0 = 0, p1 = 0;
            if (row < valid) { p0 = pack_f16x2(v.x, v.y); p1 = pack_f16x2(v.z, v.w); }
            *(uint32_t*)(smem + A2_OFF + row * 48 + seg * 8)     = p0;
            *(uint32_t*)(smem + A2_OFF + row * 48 + seg * 8 + 4) = p1;
        }
        __syncthreads();

        float c[8][4];

        // ---- layer 0: K=16 MMA from A2 x W0, bias0+ReLU -> AP0 ----
        {
            #pragma unroll
            for (int nb = 0; nb < 8; nb++)
                #pragma unroll
                for (int j = 0; j < 4; j++) c[nb][j] = 0.f;
            uint32_t a[4];
            ldsm4(a, A2b + ar * 48 + akh * 2);
            #pragma unroll
            for (int p = 0; p < 4; p++) {
                uint32_t bh[4];
                ldsm4(bh, W0b + (bn + p * 16) * 48 + bk * 2);
                mma16816(c[2 * p],     a, bh[0], bh[1]);
                mma16816(c[2 * p + 1], a, bh[2], bh[3]);
            }
            const float* bl_ = bias;    // b0
            #pragma unroll
            for (int nb = 0; nb < 8; nb++) {
                int col = cc0 + nb * 8;
                float be = bl_[col], bo = bl_[col + 1];
                uint32_t p0 = pack_f16x2(fmaxf(c[nb][0] + be, 0.f), fmaxf(c[nb][1] + bo, 0.f));
                uint32_t p1 = pack_f16x2(fmaxf(c[nb][2] + be, 0.f), fmaxf(c[nb][3] + bo, 0.f));
                *(uint32_t*)(smem + AP0_OFF + mswz(r0, col))     = p0;
                *(uint32_t*)(smem + AP0_OFF + mswz(r0 + 8, col)) = p1;
            }
        }
        __syncthreads();

        // ---- layers 1..3: single-pass fp16 MMA, ping-pong activations ----
        #pragma unroll
        for (int L = 0; L < 3; L++) {
            const uint32_t Acur = AB[L & 1];
            #pragma unroll
            for (int nb = 0; nb < 8; nb++)
                #pragma unroll
                for (int j = 0; j < 4; j++) c[nb][j] = 0.f;

            const uint32_t Wb = WB[L];
            #pragma unroll
            for (int kb = 0; kb < 8; kb++) {
                uint32_t a[4];
                ldsm4(a, Acur + mswz(ar, kb * 16 + akh));
                #pragma unroll
                for (int p = 0; p < 4; p++) {
                    uint32_t bh[4];
                    ldsm4(bh, Wb + mswz(bn + p * 16, kb * 16 + bk));
                    mma16816(c[2 * p],     a, bh[0], bh[1]);
                    mma16816(c[2 * p + 1], a, bh[2], bh[3]);
                }
            }

            if (L < 2) {
                // bias + ReLU -> fp16 -> other activation buffer
                const float* bl_ = bias + (L + 1) * HH;
                const uint32_t Anxt = AB[(L + 1) & 1] - smem_base;
                #pragma unroll
                for (int nb = 0; nb < 8; nb++) {
                    int col = cc0 + nb * 8;
                    float be = bl_[col], bo = bl_[col + 1];
                    uint32_t p0 = pack_f16x2(fmaxf(c[nb][0] + be, 0.f), fmaxf(c[nb][1] + bo, 0.f));
                    uint32_t p1 = pack_f16x2(fmaxf(c[nb][2] + be, 0.f), fmaxf(c[nb][3] + bo, 0.f));
                    *(uint32_t*)(smem + Anxt + mswz(r0, col))     = p0;
                    *(uint32_t*)(smem + Anxt + mswz(r0 + 8, col)) = p1;
                }
                __syncthreads();
            } else {
                // final: bias + ReLU + masked column-sum (pooling partial)
                const float* b3s = bias + 3 * HH;
                const float m0 = (r0 < valid) ? 1.f : 0.f;
                const float m1 = (r0 + 8 < valid) ? 1.f : 0.f;
                #pragma unroll
                for (int nb = 0; nb < 8; nb++) {
                    int col = cc0 + nb * 8;
                    float be = b3s[col], bo = b3s[col + 1];
                    float s0 = m0 * fmaxf(c[nb][0] + be, 0.f) + m1 * fmaxf(c[nb][2] + be, 0.f);
                    float s1 = m0 * fmaxf(c[nb][1] + bo, 0.f) + m1 * fmaxf(c[nb][3] + bo, 0.f);
                    #pragma unroll
                    for (int off = 4; off < 32; off <<= 1) {
                        s0 += __shfl_xor_sync(0xFFFFFFFFu, s0, off);
                        s1 += __shfl_xor_sync(0xFFFFFFFFu, s1, off);
                    }
                    if (lane < 4) {
                        int cc = ch * 64 + nb * 8 + lane * 2;
                        red[rg * HH + cc]     = s0;
                        red[rg * HH + cc + 1] = s1;
                    }
                }
                __syncthreads();
                if (tid < HH) {
                    float s = 0.f;
                    #pragma unroll
                    for (int g = 0; g < 8; g++) s += red[g * HH + tid];
                    g_partial[(size_t)slot * HH + tid] = s;
                }
            }
        }
    }
}

// ============================================================================
// Kernel 3: rho (fp32 SIMT), deterministic fixed-order partial reduction
// ============================================================================
__global__ void __launch_bounds__(128)
rho_kernel(const float* __restrict__ w0, const float* __restrict__ b0,
           const float* __restrict__ w1, const float* __restrict__ b1,
           const float* __restrict__ w2, const float* __restrict__ b2,
           const float* __restrict__ w3, const float* __restrict__ b3,
           float* __restrict__ out) {
    __shared__ float s_in[HH];
    __shared__ float s_red[HH];
    const int b = blockIdx.x, j = threadIdx.x;
    const int len = g_len[b];
    const int nt = (len + 127) >> 7;

    float acc = 0.f;
    for (int t = 0; t < nt; t++)
        acc += g_partial[((size_t)b * TILES_PER_B + t) * HH + j];
    s_in[j] = acc;
    __syncthreads();

    const float* Ws[3] = { w0, w1, w2 };
    const float* Bs[3] = { b0, b1, b2 };
    for (int L = 0; L < 3; L++) {
        float v = Bs[L][j];
        const float* W = Ws[L];
        #pragma unroll 8
        for (int k = 0; k < HH; k++) v += s_in[k] * W[k * HH + j];
        v = fmaxf(v, 0.f);
        __syncthreads();
        s_in[j] = v;
        __syncthreads();
    }
    s_red[j] = s_in[j] * w3[j];
    __syncthreads();
    if (j == 0) {
        float s = b3[0];
        #pragma unroll 8
        for (int k = 0; k < HH; k++) s += s_red[k];
        out[b] = s;
    }
}

// ============================================================================
// kernel_launch
// ============================================================================
extern "C" void kernel_launch(void* const* d_in, const int* in_sizes, int n_in,
                              void* d_out, int out_size) {
    const float* x   = (const float*)d_in[0];
    const float* pw0 = (const float*)d_in[1];
    const float* pb0 = (const float*)d_in[2];
    const float* pw1 = (const float*)d_in[3];
    const float* pb1 = (const float*)d_in[4];
    const float* pw2 = (const float*)d_in[5];
    const float* pb2 = (const float*)d_in[6];
    const float* pw3 = (const float*)d_in[7];
    const float* pb3 = (const float*)d_in[8];
    const float* rw0 = (const float*)d_in[9];
    const float* rb0 = (const float*)d_in[10];
    const float* rw1 = (const float*)d_in[11];
    const float* rb1 = (const float*)d_in[12];
    const float* rw2 = (const float*)d_in[13];
    const float* rb2 = (const float*)d_in[14];
    const float* rw3 = (const float*)d_in[15];
    const float* rb3 = (const float*)d_in[16];

    static bool attr_set = false;
    if (!attr_set) {
        cudaFuncSetAttribute(phi_kernel, cudaFuncAttributeMaxDynamicSharedMemorySize, SMEM_TOTAL);
        attr_set = true;
    }

    reset_kernel<<<1, 1>>>();
    len_kernel<<<BB / 8, 256>>>(x);
    phi_kernel<<<PHI_GRID, PHI_THREADS, SMEM_TOTAL>>>(x, pw0, pb0, pw1, pb1, pw2, pb2, pw3, pb3);
    rho_kernel<<<BB, 128>>>(rw0, rb0, rw1, rb1, rw2, rb2, rw3, rb3, (float*)d_out);
}